// round 3
// baseline (speedup 1.0000x reference)
#include <cuda_runtime.h>
#include <math.h>
#include <float.h>

// Problem dims
#define T_SEQ 256
#define BATCH 512
#define IND   128
#define H1D   100
#define G1D   400     // 4*H1
#define H2D   128
#define G2D   512     // 4*H2
#define NC    19

typedef unsigned long long u64;

__device__ __forceinline__ void ffma2(u64 &d, u64 a, u64 b) {
    asm("fma.rn.f32x2 %0, %1, %2, %0;" : "+l"(d) : "l"(a), "l"(b));
}
__device__ __forceinline__ u64 pack2(float x, float y) {
    u64 r; asm("mov.b64 %0, {%1, %2};" : "=l"(r) : "f"(x), "f"(y)); return r;
}
__device__ __forceinline__ float2 unpk(u64 v) {
    float2 r; asm("mov.b64 {%0, %1}, %2;" : "=f"(r.x), "=f"(r.y) : "l"(v)); return r;
}

// ---------------- scratch ---------------------------------------------------
__device__ float g_zx1[256u*400u*512u];   // [T][G1][B]
__device__ float g_h1 [256u*512u*100u];   // [(t,b)][H1]  row-major for gemm2 A
__device__ float g_zx2[256u*512u*512u];   // [T][G2][B]
__device__ float g_h2 [512u*128u];        // [B][H2]

// ---------------- feedforward GEMM: C[t][n][b] = A(MxK)*B(KxN) + bias -------
// mode==1: A row m=(t*512+b) gathered from x[b][t][:]; mode==0: contiguous.
#define BM 64
#define BN 64
#define KMAX 128
#define AP 68

__global__ __launch_bounds__(256, 2)
void gemm_ff(const float* __restrict__ A, const float* __restrict__ Bw,
             const float* __restrict__ bias, float* __restrict__ C,
             int M, int N, int K, int mode)
{
    extern __shared__ __align__(16) float sm[];
    float* As  = sm;                                   // [KMAX][AP]  A^T tile
    u64*   Bs  = reinterpret_cast<u64*>(sm + KMAX*AP); // [KMAX][BN]  dup-packed

    const int tid = threadIdx.x;
    const int m0 = blockIdx.x * BM;
    const int n0 = blockIdx.y * BN;

    for (int idx = tid; idx < BM * K; idx += 256) {
        int mloc = idx / K;
        int k = idx - mloc * K;
        int m = m0 + mloc;
        size_t arow;
        if (mode) { int t = m >> 9; int b = m & 511; arow = ((size_t)(b * T_SEQ + t)) * IND; }
        else      { arow = (size_t)m * K; }
        As[k * AP + mloc] = A[arow + k];
    }
    for (int idx = tid; idx < K * BN; idx += 256) {
        int k = idx >> 6;
        int n = idx & 63;
        int gn = n0 + n;
        float v = (gn < N) ? Bw[(size_t)k * N + gn] : 0.f;
        Bs[k * BN + n] = pack2(v, v);
    }
    __syncthreads();

    const int tx = tid & 15, ty = tid >> 4;
    u64 acc2[2][4];
#pragma unroll
    for (int i = 0; i < 2; i++)
#pragma unroll
        for (int j = 0; j < 4; j++) acc2[i][j] = 0ull;

#pragma unroll 4
    for (int k = 0; k < K; ++k) {
        ulonglong2 av = *reinterpret_cast<const ulonglong2*>(&As[k * AP + ty * 4]);
        ulonglong2 b01 = *reinterpret_cast<const ulonglong2*>(&Bs[k * BN + tx * 4]);
        ulonglong2 b23 = *reinterpret_cast<const ulonglong2*>(&Bs[k * BN + tx * 4 + 2]);
        ffma2(acc2[0][0], av.x, b01.x); ffma2(acc2[0][1], av.x, b01.y);
        ffma2(acc2[0][2], av.x, b23.x); ffma2(acc2[0][3], av.x, b23.y);
        ffma2(acc2[1][0], av.y, b01.x); ffma2(acc2[1][1], av.y, b01.y);
        ffma2(acc2[1][2], av.y, b23.x); ffma2(acc2[1][3], av.y, b23.y);
    }

    // C layout: [t][n][b]; tile spans one t (BM=64 divides 512)
    const int t = m0 >> 9;
    const int bb = (m0 & 511) + ty * 4;
#pragma unroll
    for (int j = 0; j < 4; j++) {
        int n = n0 + tx * 4 + j;
        if (n < N) {
            float bn = bias[n];
            float2 p = unpk(acc2[0][j]);
            float2 q = unpk(acc2[1][j]);
            float4 v = make_float4(p.x + bn, p.y + bn, q.x + bn, q.y + bn);
            *reinterpret_cast<float4*>(&C[((size_t)t * N + n) * BATCH + bb]) = v;
        }
    }
}

// ---------------- layer-1 scan ---------------------------------------------
// tid = 4j+k ; col = k*H1 + j (gate k of unit j). All 4 gates of j in one
// lane-quad -> gate exchange is warp-local. One block barrier per step;
// double-buffered hT. Pad threads (j>=100) clamp to j=99 (benign redundancy).
#define U1REGJ 80
#define U1SMJ  20
#define H1P    104   // padded hT row
#define ZSP    20    // padded zs row (conflict-free stride)
__global__ __launch_bounds__(512, 1)
void lstm_scan1(const float* __restrict__ zx, const float* __restrict__ U,
                float* __restrict__ hout)
{
    __shared__ __align__(16) float U1sT[512 * U1SMJ];
    __shared__ __align__(16) float hT[2 * 4 * H1P];
    __shared__ __align__(16) float zs[128 * ZSP];

    const int tid = threadIdx.x;
    const int j  = tid >> 2;
    const int k  = tid & 3;
    const int jc = (j < H1D) ? j : (H1D - 1);
    const int col = k * H1D + jc;
    const int b0 = blockIdx.x * 4;

    u64 Up[U1REGJ / 2];
#pragma unroll
    for (int p = 0; p < U1REGJ / 2; ++p)
        Up[p] = pack2(U[(2 * p) * G1D + col], U[(2 * p + 1) * G1D + col]);
#pragma unroll
    for (int jj = 0; jj < U1SMJ; ++jj)
        U1sT[tid * U1SMJ + jj] = U[(U1REGJ + jj) * G1D + col];
    for (int i = tid; i < 2 * 4 * H1P; i += 512) hT[i] = 0.f;

    float c = 0.f;
    __syncthreads();

#pragma unroll 1
    for (int t = 0; t < T_SEQ; ++t) {
        const float* hp = hT + (t & 1) * (4 * H1P);
        float4 xz = *reinterpret_cast<const float4*>(
            &zx[((size_t)t * G1D + col) * BATCH + b0]);
        u64 ac0 = 0ull, ac1 = 0ull, ac2 = 0ull, ac3 = 0ull;
#pragma unroll
        for (int p4 = 0; p4 < U1REGJ / 4; ++p4) {
            int j0 = 4 * p4;
            ulonglong2 h0 = *reinterpret_cast<const ulonglong2*>(&hp[0 * H1P + j0]);
            ulonglong2 h1 = *reinterpret_cast<const ulonglong2*>(&hp[1 * H1P + j0]);
            ulonglong2 h2 = *reinterpret_cast<const ulonglong2*>(&hp[2 * H1P + j0]);
            ulonglong2 h3 = *reinterpret_cast<const ulonglong2*>(&hp[3 * H1P + j0]);
            u64 ua = Up[2 * p4], ub = Up[2 * p4 + 1];
            ffma2(ac0, h0.x, ua); ffma2(ac0, h0.y, ub);
            ffma2(ac1, h1.x, ua); ffma2(ac1, h1.y, ub);
            ffma2(ac2, h2.x, ua); ffma2(ac2, h2.y, ub);
            ffma2(ac3, h3.x, ua); ffma2(ac3, h3.y, ub);
        }
#pragma unroll
        for (int q = 0; q < U1SMJ / 4; ++q) {
            int j0 = U1REGJ + 4 * q;
            ulonglong2 uu = *reinterpret_cast<const ulonglong2*>(&U1sT[tid * U1SMJ + 4 * q]);
            ulonglong2 h0 = *reinterpret_cast<const ulonglong2*>(&hp[0 * H1P + j0]);
            ulonglong2 h1 = *reinterpret_cast<const ulonglong2*>(&hp[1 * H1P + j0]);
            ulonglong2 h2 = *reinterpret_cast<const ulonglong2*>(&hp[2 * H1P + j0]);
            ulonglong2 h3 = *reinterpret_cast<const ulonglong2*>(&hp[3 * H1P + j0]);
            ffma2(ac0, h0.x, uu.x); ffma2(ac0, h0.y, uu.y);
            ffma2(ac1, h1.x, uu.x); ffma2(ac1, h1.y, uu.y);
            ffma2(ac2, h2.x, uu.x); ffma2(ac2, h2.y, uu.y);
            ffma2(ac3, h3.x, uu.x); ffma2(ac3, h3.y, uu.y);
        }
        float2 s0 = unpk(ac0), s1 = unpk(ac1), s2 = unpk(ac2), s3 = unpk(ac3);
        float a0 = s0.x + s0.y + xz.x;
        float a1 = s1.x + s1.y + xz.y;
        float a2 = s2.x + s2.y + xz.z;
        float a3 = s3.x + s3.y + xz.w;
        if (k == 2) {
            a0 = fmaxf(a0, 0.f); a1 = fmaxf(a1, 0.f);
            a2 = fmaxf(a2, 0.f); a3 = fmaxf(a3, 0.f);
        } else {
            a0 = 1.f / (1.f + __expf(-a0));
            a1 = 1.f / (1.f + __expf(-a1));
            a2 = 1.f / (1.f + __expf(-a2));
            a3 = 1.f / (1.f + __expf(-a3));
        }
        // warp-local gate exchange: zs[j][gate k][rows 0..3]
        *reinterpret_cast<float4*>(&zs[j * ZSP + k * 4]) = make_float4(a0, a1, a2, a3);
        __syncwarp();
        float gi = zs[j * ZSP + 0  + k];
        float gf = zs[j * ZSP + 4  + k];
        float gg = zs[j * ZSP + 8  + k];
        float go = zs[j * ZSP + 12 + k];
        c = fmaf(gf, c, gi * gg);
        float h = go * fmaxf(c, 0.f);
        hT[(1 - (t & 1)) * (4 * H1P) + k * H1P + jc] = h;   // benign dup for j>=100
        if (j < H1D)
            hout[((size_t)t * BATCH + b0 + k) * H1D + j] = h;
        __syncthreads();
    }
}

// ---------------- layer-2 scan ---------------------------------------------
#define U2REGJ 64
#define U2SMJ  64
#define U2P    68
__global__ __launch_bounds__(512, 1)
void lstm_scan2(const float* __restrict__ zx, const float* __restrict__ U,
                float* __restrict__ h2out)
{
    extern __shared__ __align__(16) float sm2[];
    float* U2sT = sm2;                       // [512][U2P]
    float* hT   = sm2 + 512 * U2P;           // [2][4][H2D]
    float* zs   = hT + 2 * 4 * H2D;          // [128][ZSP]

    const int tid = threadIdx.x;
    const int j = tid >> 2;
    const int k = tid & 3;
    const int col = k * H2D + j;
    const int b0 = blockIdx.x * 4;

    u64 Up[U2REGJ / 2];
#pragma unroll
    for (int p = 0; p < U2REGJ / 2; ++p)
        Up[p] = pack2(U[(2 * p) * G2D + col], U[(2 * p + 1) * G2D + col]);
#pragma unroll
    for (int jj = 0; jj < U2SMJ; ++jj)
        U2sT[tid * U2P + jj] = U[(size_t)(U2REGJ + jj) * G2D + col];
    for (int i = tid; i < 2 * 4 * H2D; i += 512) hT[i] = 0.f;

    float c = 0.f;
    __syncthreads();

#pragma unroll 1
    for (int t = 0; t < T_SEQ; ++t) {
        const float* hp = hT + (t & 1) * (4 * H2D);
        float4 xz = *reinterpret_cast<const float4*>(
            &zx[((size_t)t * G2D + col) * BATCH + b0]);
        u64 ac0 = 0ull, ac1 = 0ull, ac2 = 0ull, ac3 = 0ull;
#pragma unroll
        for (int p4 = 0; p4 < U2REGJ / 4; ++p4) {
            int j0 = 4 * p4;
            ulonglong2 h0 = *reinterpret_cast<const ulonglong2*>(&hp[0 * H2D + j0]);
            ulonglong2 h1 = *reinterpret_cast<const ulonglong2*>(&hp[1 * H2D + j0]);
            ulonglong2 h2 = *reinterpret_cast<const ulonglong2*>(&hp[2 * H2D + j0]);
            ulonglong2 h3 = *reinterpret_cast<const ulonglong2*>(&hp[3 * H2D + j0]);
            u64 ua = Up[2 * p4], ub = Up[2 * p4 + 1];
            ffma2(ac0, h0.x, ua); ffma2(ac0, h0.y, ub);
            ffma2(ac1, h1.x, ua); ffma2(ac1, h1.y, ub);
            ffma2(ac2, h2.x, ua); ffma2(ac2, h2.y, ub);
            ffma2(ac3, h3.x, ua); ffma2(ac3, h3.y, ub);
        }
#pragma unroll
        for (int q = 0; q < U2SMJ / 4; ++q) {
            int j0 = U2REGJ + 4 * q;
            ulonglong2 uu = *reinterpret_cast<const ulonglong2*>(&U2sT[tid * U2P + 4 * q]);
            ulonglong2 h0 = *reinterpret_cast<const ulonglong2*>(&hp[0 * H2D + j0]);
            ulonglong2 h1 = *reinterpret_cast<const ulonglong2*>(&hp[1 * H2D + j0]);
            ulonglong2 h2 = *reinterpret_cast<const ulonglong2*>(&hp[2 * H2D + j0]);
            ulonglong2 h3 = *reinterpret_cast<const ulonglong2*>(&hp[3 * H2D + j0]);
            ffma2(ac0, h0.x, uu.x); ffma2(ac0, h0.y, uu.y);
            ffma2(ac1, h1.x, uu.x); ffma2(ac1, h1.y, uu.y);
            ffma2(ac2, h2.x, uu.x); ffma2(ac2, h2.y, uu.y);
            ffma2(ac3, h3.x, uu.x); ffma2(ac3, h3.y, uu.y);
        }
        float2 s0 = unpk(ac0), s1 = unpk(ac1), s2 = unpk(ac2), s3 = unpk(ac3);
        float a0 = s0.x + s0.y + xz.x;
        float a1 = s1.x + s1.y + xz.y;
        float a2 = s2.x + s2.y + xz.z;
        float a3 = s3.x + s3.y + xz.w;
        if (k == 2) {
            a0 = fmaxf(a0, 0.f); a1 = fmaxf(a1, 0.f);
            a2 = fmaxf(a2, 0.f); a3 = fmaxf(a3, 0.f);
        } else {
            a0 = 1.f / (1.f + __expf(-a0));
            a1 = 1.f / (1.f + __expf(-a1));
            a2 = 1.f / (1.f + __expf(-a2));
            a3 = 1.f / (1.f + __expf(-a3));
        }
        *reinterpret_cast<float4*>(&zs[j * ZSP + k * 4]) = make_float4(a0, a1, a2, a3);
        __syncwarp();
        float gi = zs[j * ZSP + 0  + k];
        float gf = zs[j * ZSP + 4  + k];
        float gg = zs[j * ZSP + 8  + k];
        float go = zs[j * ZSP + 12 + k];
        c = fmaf(gf, c, gi * gg);
        float h = go * fmaxf(c, 0.f);
        hT[(1 - (t & 1)) * (4 * H2D) + k * H2D + j] = h;
        if (t == T_SEQ - 1) h2out[(b0 + k) * H2D + j] = h;
        __syncthreads();
    }
}

// ---------------- dense head + softmax -------------------------------------
__global__ void head_kernel(const float* __restrict__ h2, const float* __restrict__ Wd,
                            const float* __restrict__ bd, float* __restrict__ out)
{
    __shared__ float hsh[H2D];
    const int b = blockIdx.x;
    const int lane = threadIdx.x;
    for (int j = lane; j < H2D; j += 32) hsh[j] = h2[b * H2D + j];
    __syncthreads();

    float acc = 0.f;
    if (lane < NC) {
        acc = bd[lane];
#pragma unroll
        for (int j = 0; j < H2D; ++j) acc = fmaf(hsh[j], Wd[j * NC + lane], acc);
    }
    float v = (lane < NC) ? acc : -FLT_MAX;
#pragma unroll
    for (int off = 16; off > 0; off >>= 1)
        v = fmaxf(v, __shfl_xor_sync(0xffffffffu, v, off));
    float e = (lane < NC) ? expf(acc - v) : 0.f;
    float s = e;
#pragma unroll
    for (int off = 16; off > 0; off >>= 1)
        s += __shfl_xor_sync(0xffffffffu, s, off);
    if (lane < NC) out[b * NC + lane] = e / s;
}

// ---------------- launch ----------------------------------------------------
extern "C" void kernel_launch(void* const* d_in, const int* in_sizes, int n_in,
                              void* d_out, int out_size)
{
    const float* x  = (const float*)d_in[0];
    const float* W1 = (const float*)d_in[1];
    const float* U1 = (const float*)d_in[2];
    const float* b1 = (const float*)d_in[3];
    const float* W2 = (const float*)d_in[4];
    const float* U2 = (const float*)d_in[5];
    const float* b2 = (const float*)d_in[6];
    const float* Wd = (const float*)d_in[7];
    const float* bd = (const float*)d_in[8];
    float* out = (float*)d_out;

    const int gemm_smem  = KMAX * AP * 4 + KMAX * BN * 8;               // 100352
    const int scan2_smem = (512 * U2P + 2 * 4 * H2D + 128 * ZSP) * 4;   // 153600
    cudaFuncSetAttribute(gemm_ff,    cudaFuncAttributeMaxDynamicSharedMemorySize, gemm_smem);
    cudaFuncSetAttribute(lstm_scan2, cudaFuncAttributeMaxDynamicSharedMemorySize, scan2_smem);

    float *zx1p, *h1p, *zx2p, *h2p;
    cudaGetSymbolAddress((void**)&zx1p, g_zx1);
    cudaGetSymbolAddress((void**)&h1p,  g_h1);
    cudaGetSymbolAddress((void**)&zx2p, g_zx2);
    cudaGetSymbolAddress((void**)&h2p,  g_h2);

    const int M = T_SEQ * BATCH;

    gemm_ff<<<dim3(M / BM, (G1D + BN - 1) / BN), 256, gemm_smem>>>(
        x, W1, b1, zx1p, M, G1D, IND, 1);

    lstm_scan1<<<BATCH / 4, 512>>>(zx1p, U1, h1p);

    gemm_ff<<<dim3(M / BM, G2D / BN), 256, gemm_smem>>>(
        h1p, W2, b2, zx2p, M, G2D, H1D, 0);

    lstm_scan2<<<BATCH / 4, 512, scan2_smem>>>(zx2p, U2, h2p);

    head_kernel<<<BATCH, 32>>>(h2p, Wd, bd, out);
}

// round 4
// speedup vs baseline: 1.5633x; 1.5633x over previous
#include <cuda_runtime.h>
#include <math.h>
#include <float.h>

// Problem dims
#define T_SEQ 256
#define BATCH 512
#define IND   128
#define H1D   100
#define G1D   400     // 4*H1
#define H2D   128
#define G2D   512     // 4*H2
#define NC    19

typedef unsigned long long u64;

__device__ __forceinline__ void ffma2(u64 &d, u64 a, u64 b) {
    asm("fma.rn.f32x2 %0, %1, %2, %0;" : "+l"(d) : "l"(a), "l"(b));
}
__device__ __forceinline__ u64 pack2(float x, float y) {
    u64 r; asm("mov.b64 %0, {%1, %2};" : "=l"(r) : "f"(x), "f"(y)); return r;
}
__device__ __forceinline__ float2 unpk(u64 v) {
    float2 r; asm("mov.b64 {%0, %1}, %2;" : "=f"(r.x), "=f"(r.y) : "l"(v)); return r;
}

// ---------------- scratch ---------------------------------------------------
__device__ float g_zx1[256u*512u*400u];   // [(t,b)][G1]
__device__ float g_h1 [256u*512u*100u];   // [(t,b)][H1]
__device__ float g_zx2[256u*512u*512u];   // [(t,b)][G2]
__device__ float g_h2 [512u*128u];        // [B][H2]

// ---------------- feedforward GEMM (R2-proven): C = A(MxK)*B(KxN) + bias ----
#define BM 64
#define BN 64
#define KMAX 128
#define AP 68

__global__ __launch_bounds__(256, 3)
void gemm_ff(const float* __restrict__ A, const float* __restrict__ Bw,
             const float* __restrict__ bias, float* __restrict__ C,
             int M, int N, int K, int mode)
{
    extern __shared__ float sm[];
    float* As = sm;                 // [KMAX][AP] transposed A tile
    float* Bs = sm + KMAX * AP;     // [KMAX][BN]

    const int tid = threadIdx.x;
    const int m0 = blockIdx.x * BM;
    const int n0 = blockIdx.y * BN;

    for (int idx = tid; idx < BM * K; idx += 256) {
        int mloc = idx / K;
        int k = idx - mloc * K;
        int m = m0 + mloc;
        size_t arow;
        if (mode) { int t = m >> 9; int b = m & 511; arow = ((size_t)(b * T_SEQ + t)) * IND; }
        else      { arow = (size_t)m * K; }
        As[k * AP + mloc] = A[arow + k];
    }
    for (int idx = tid; idx < K * BN; idx += 256) {
        int k = idx >> 6;
        int n = idx & 63;
        int gn = n0 + n;
        Bs[k * BN + n] = (gn < N) ? Bw[(size_t)k * N + gn] : 0.f;
    }
    __syncthreads();

    const int tx = tid & 15, ty = tid >> 4;
    u64 acc2[2][4];
#pragma unroll
    for (int i = 0; i < 2; i++)
#pragma unroll
        for (int j = 0; j < 4; j++) acc2[i][j] = 0ull;

#pragma unroll 4
    for (int k = 0; k < K; ++k) {
        ulonglong2 av = *reinterpret_cast<const ulonglong2*>(&As[k * AP + ty * 4]);
        float4 bv = *reinterpret_cast<const float4*>(&Bs[k * BN + tx * 4]);
        u64 b0 = pack2(bv.x, bv.x);
        u64 b1 = pack2(bv.y, bv.y);
        u64 b2 = pack2(bv.z, bv.z);
        u64 b3 = pack2(bv.w, bv.w);
        ffma2(acc2[0][0], av.x, b0); ffma2(acc2[0][1], av.x, b1);
        ffma2(acc2[0][2], av.x, b2); ffma2(acc2[0][3], av.x, b3);
        ffma2(acc2[1][0], av.y, b0); ffma2(acc2[1][1], av.y, b1);
        ffma2(acc2[1][2], av.y, b2); ffma2(acc2[1][3], av.y, b3);
    }

    float accf[4][4];
#pragma unroll
    for (int j = 0; j < 4; j++) {
        float2 p = unpk(acc2[0][j]);
        float2 q = unpk(acc2[1][j]);
        accf[0][j] = p.x; accf[1][j] = p.y;
        accf[2][j] = q.x; accf[3][j] = q.y;
    }

#pragma unroll
    for (int i = 0; i < 4; i++) {
        int m = m0 + ty * 4 + i;
        int n = n0 + tx * 4;
        float* cp = &C[(size_t)m * N + n];
        if (n + 3 < N) {
            float4 v;
            v.x = accf[i][0] + bias[n + 0];
            v.y = accf[i][1] + bias[n + 1];
            v.z = accf[i][2] + bias[n + 2];
            v.w = accf[i][3] + bias[n + 3];
            *reinterpret_cast<float4*>(cp) = v;
        } else {
#pragma unroll
            for (int j = 0; j < 4; j++)
                if (n + j < N) cp[j] = accf[i][j] + bias[n + j];
        }
    }
}

// ---------------- layer-1 scan ---------------------------------------------
// tid=4j+k, col=k*H1+j. Warp-local gate exchange; ONE block barrier/step;
// double-buffered hT; z prefetch (t+1 issued at top of step t).
// zx layout [(t,b)][G1]: per (warp,k) reads are 32B-chunk coalesced.
#define U1REGJ 80
#define U1SMJ  20
#define H1P    104
#define ZSP    20
__global__ __launch_bounds__(512, 1)
void lstm_scan1(const float* __restrict__ zx, const float* __restrict__ U,
                float* __restrict__ hout)
{
    __shared__ __align__(16) float U1sT[512 * U1SMJ];
    __shared__ __align__(16) float hT[2 * 4 * H1P];
    __shared__ __align__(16) float zs[128 * ZSP];

    const int tid = threadIdx.x;
    const int j  = tid >> 2;
    const int k  = tid & 3;
    const int jc = (j < H1D) ? j : (H1D - 1);
    const int col = k * H1D + jc;
    const int b0 = blockIdx.x * 4;

    u64 Up[U1REGJ / 2];
#pragma unroll
    for (int p = 0; p < U1REGJ / 2; ++p)
        Up[p] = pack2(U[(2 * p) * G1D + col], U[(2 * p + 1) * G1D + col]);
#pragma unroll
    for (int jj = 0; jj < U1SMJ; ++jj)
        U1sT[tid * U1SMJ + jj] = U[(U1REGJ + jj) * G1D + col];
    for (int i = tid; i < 2 * 4 * H1P; i += 512) hT[i] = 0.f;

    float c = 0.f;
    // prefetch z(0)
    const float* zb = zx + col;
    float z0 = zb[((size_t)0 * BATCH + b0 + 0) * G1D];
    float z1 = zb[((size_t)0 * BATCH + b0 + 1) * G1D];
    float z2 = zb[((size_t)0 * BATCH + b0 + 2) * G1D];
    float z3 = zb[((size_t)0 * BATCH + b0 + 3) * G1D];
    __syncthreads();

#pragma unroll 1
    for (int t = 0; t < T_SEQ; ++t) {
        // issue next-step z loads early (covered by matvec + barrier)
        int tn = (t + 1 < T_SEQ) ? (t + 1) : t;
        float n0 = zb[((size_t)tn * BATCH + b0 + 0) * G1D];
        float n1 = zb[((size_t)tn * BATCH + b0 + 1) * G1D];
        float n2 = zb[((size_t)tn * BATCH + b0 + 2) * G1D];
        float n3 = zb[((size_t)tn * BATCH + b0 + 3) * G1D];

        const float* hp = hT + (t & 1) * (4 * H1P);
        u64 ac0 = 0ull, ac1 = 0ull, ac2 = 0ull, ac3 = 0ull;
#pragma unroll
        for (int p4 = 0; p4 < U1REGJ / 4; ++p4) {
            int j0 = 4 * p4;
            ulonglong2 h0 = *reinterpret_cast<const ulonglong2*>(&hp[0 * H1P + j0]);
            ulonglong2 h1 = *reinterpret_cast<const ulonglong2*>(&hp[1 * H1P + j0]);
            ulonglong2 h2 = *reinterpret_cast<const ulonglong2*>(&hp[2 * H1P + j0]);
            ulonglong2 h3 = *reinterpret_cast<const ulonglong2*>(&hp[3 * H1P + j0]);
            u64 ua = Up[2 * p4], ub = Up[2 * p4 + 1];
            ffma2(ac0, h0.x, ua); ffma2(ac0, h0.y, ub);
            ffma2(ac1, h1.x, ua); ffma2(ac1, h1.y, ub);
            ffma2(ac2, h2.x, ua); ffma2(ac2, h2.y, ub);
            ffma2(ac3, h3.x, ua); ffma2(ac3, h3.y, ub);
        }
#pragma unroll
        for (int q = 0; q < U1SMJ / 4; ++q) {
            int j0 = U1REGJ + 4 * q;
            ulonglong2 uu = *reinterpret_cast<const ulonglong2*>(&U1sT[tid * U1SMJ + 4 * q]);
            ulonglong2 h0 = *reinterpret_cast<const ulonglong2*>(&hp[0 * H1P + j0]);
            ulonglong2 h1 = *reinterpret_cast<const ulonglong2*>(&hp[1 * H1P + j0]);
            ulonglong2 h2 = *reinterpret_cast<const ulonglong2*>(&hp[2 * H1P + j0]);
            ulonglong2 h3 = *reinterpret_cast<const ulonglong2*>(&hp[3 * H1P + j0]);
            ffma2(ac0, h0.x, uu.x); ffma2(ac0, h0.y, uu.y);
            ffma2(ac1, h1.x, uu.x); ffma2(ac1, h1.y, uu.y);
            ffma2(ac2, h2.x, uu.x); ffma2(ac2, h2.y, uu.y);
            ffma2(ac3, h3.x, uu.x); ffma2(ac3, h3.y, uu.y);
        }
        float2 s0 = unpk(ac0), s1 = unpk(ac1), s2 = unpk(ac2), s3 = unpk(ac3);
        float a0 = s0.x + s0.y + z0;
        float a1 = s1.x + s1.y + z1;
        float a2 = s2.x + s2.y + z2;
        float a3 = s3.x + s3.y + z3;
        if (k == 2) {
            a0 = fmaxf(a0, 0.f); a1 = fmaxf(a1, 0.f);
            a2 = fmaxf(a2, 0.f); a3 = fmaxf(a3, 0.f);
        } else {
            a0 = 1.f / (1.f + __expf(-a0));
            a1 = 1.f / (1.f + __expf(-a1));
            a2 = 1.f / (1.f + __expf(-a2));
            a3 = 1.f / (1.f + __expf(-a3));
        }
        *reinterpret_cast<float4*>(&zs[j * ZSP + k * 4]) = make_float4(a0, a1, a2, a3);
        __syncwarp();
        float gi = zs[j * ZSP + 0  + k];
        float gf = zs[j * ZSP + 4  + k];
        float gg = zs[j * ZSP + 8  + k];
        float go = zs[j * ZSP + 12 + k];
        c = fmaf(gf, c, gi * gg);
        float h = go * fmaxf(c, 0.f);
        hT[(1 - (t & 1)) * (4 * H1P) + k * H1P + jc] = h;   // dup for j>=100: same value
        if (j < H1D)
            hout[((size_t)t * BATCH + b0 + k) * H1D + j] = h;
        z0 = n0; z1 = n1; z2 = n2; z3 = n3;
        __syncthreads();
    }
}

// ---------------- layer-2 scan ---------------------------------------------
#define U2REGJ 64
#define U2SMJ  64
#define U2P    68
__global__ __launch_bounds__(512, 1)
void lstm_scan2(const float* __restrict__ zx, const float* __restrict__ U,
                float* __restrict__ h2out)
{
    extern __shared__ __align__(16) float sm2[];
    float* U2sT = sm2;                       // [512][U2P]
    float* hT   = sm2 + 512 * U2P;           // [2][4][H2D]
    float* zs   = hT + 2 * 4 * H2D;          // [128][ZSP]

    const int tid = threadIdx.x;
    const int j = tid >> 2;
    const int k = tid & 3;
    const int col = k * H2D + j;
    const int b0 = blockIdx.x * 4;

    u64 Up[U2REGJ / 2];
#pragma unroll
    for (int p = 0; p < U2REGJ / 2; ++p)
        Up[p] = pack2(U[(2 * p) * G2D + col], U[(2 * p + 1) * G2D + col]);
#pragma unroll
    for (int jj = 0; jj < U2SMJ; ++jj)
        U2sT[tid * U2P + jj] = U[(size_t)(U2REGJ + jj) * G2D + col];
    for (int i = tid; i < 2 * 4 * H2D; i += 512) hT[i] = 0.f;

    float c = 0.f;
    const float* zb = zx + col;
    float z0 = zb[((size_t)0 * BATCH + b0 + 0) * G2D];
    float z1 = zb[((size_t)0 * BATCH + b0 + 1) * G2D];
    float z2 = zb[((size_t)0 * BATCH + b0 + 2) * G2D];
    float z3 = zb[((size_t)0 * BATCH + b0 + 3) * G2D];
    __syncthreads();

#pragma unroll 1
    for (int t = 0; t < T_SEQ; ++t) {
        int tn = (t + 1 < T_SEQ) ? (t + 1) : t;
        float n0 = zb[((size_t)tn * BATCH + b0 + 0) * G2D];
        float n1 = zb[((size_t)tn * BATCH + b0 + 1) * G2D];
        float n2 = zb[((size_t)tn * BATCH + b0 + 2) * G2D];
        float n3 = zb[((size_t)tn * BATCH + b0 + 3) * G2D];

        const float* hp = hT + (t & 1) * (4 * H2D);
        u64 ac0 = 0ull, ac1 = 0ull, ac2 = 0ull, ac3 = 0ull;
#pragma unroll
        for (int p4 = 0; p4 < U2REGJ / 4; ++p4) {
            int j0 = 4 * p4;
            ulonglong2 h0 = *reinterpret_cast<const ulonglong2*>(&hp[0 * H2D + j0]);
            ulonglong2 h1 = *reinterpret_cast<const ulonglong2*>(&hp[1 * H2D + j0]);
            ulonglong2 h2 = *reinterpret_cast<const ulonglong2*>(&hp[2 * H2D + j0]);
            ulonglong2 h3 = *reinterpret_cast<const ulonglong2*>(&hp[3 * H2D + j0]);
            u64 ua = Up[2 * p4], ub = Up[2 * p4 + 1];
            ffma2(ac0, h0.x, ua); ffma2(ac0, h0.y, ub);
            ffma2(ac1, h1.x, ua); ffma2(ac1, h1.y, ub);
            ffma2(ac2, h2.x, ua); ffma2(ac2, h2.y, ub);
            ffma2(ac3, h3.x, ua); ffma2(ac3, h3.y, ub);
        }
#pragma unroll
        for (int q = 0; q < U2SMJ / 4; ++q) {
            int j0 = U2REGJ + 4 * q;
            ulonglong2 uu = *reinterpret_cast<const ulonglong2*>(&U2sT[tid * U2P + 4 * q]);
            ulonglong2 h0 = *reinterpret_cast<const ulonglong2*>(&hp[0 * H2D + j0]);
            ulonglong2 h1 = *reinterpret_cast<const ulonglong2*>(&hp[1 * H2D + j0]);
            ulonglong2 h2 = *reinterpret_cast<const ulonglong2*>(&hp[2 * H2D + j0]);
            ulonglong2 h3 = *reinterpret_cast<const ulonglong2*>(&hp[3 * H2D + j0]);
            ffma2(ac0, h0.x, uu.x); ffma2(ac0, h0.y, uu.y);
            ffma2(ac1, h1.x, uu.x); ffma2(ac1, h1.y, uu.y);
            ffma2(ac2, h2.x, uu.x); ffma2(ac2, h2.y, uu.y);
            ffma2(ac3, h3.x, uu.x); ffma2(ac3, h3.y, uu.y);
        }
        float2 s0 = unpk(ac0), s1 = unpk(ac1), s2 = unpk(ac2), s3 = unpk(ac3);
        float a0 = s0.x + s0.y + z0;
        float a1 = s1.x + s1.y + z1;
        float a2 = s2.x + s2.y + z2;
        float a3 = s3.x + s3.y + z3;
        if (k == 2) {
            a0 = fmaxf(a0, 0.f); a1 = fmaxf(a1, 0.f);
            a2 = fmaxf(a2, 0.f); a3 = fmaxf(a3, 0.f);
        } else {
            a0 = 1.f / (1.f + __expf(-a0));
            a1 = 1.f / (1.f + __expf(-a1));
            a2 = 1.f / (1.f + __expf(-a2));
            a3 = 1.f / (1.f + __expf(-a3));
        }
        *reinterpret_cast<float4*>(&zs[j * ZSP + k * 4]) = make_float4(a0, a1, a2, a3);
        __syncwarp();
        float gi = zs[j * ZSP + 0  + k];
        float gf = zs[j * ZSP + 4  + k];
        float gg = zs[j * ZSP + 8  + k];
        float go = zs[j * ZSP + 12 + k];
        c = fmaf(gf, c, gi * gg);
        float h = go * fmaxf(c, 0.f);
        hT[(1 - (t & 1)) * (4 * H2D) + k * H2D + j] = h;
        if (t == T_SEQ - 1) h2out[(b0 + k) * H2D + j] = h;
        z0 = n0; z1 = n1; z2 = n2; z3 = n3;
        __syncthreads();
    }
}

// ---------------- dense head + softmax -------------------------------------
__global__ void head_kernel(const float* __restrict__ h2, const float* __restrict__ Wd,
                            const float* __restrict__ bd, float* __restrict__ out)
{
    __shared__ float hsh[H2D];
    const int b = blockIdx.x;
    const int lane = threadIdx.x;
    for (int j = lane; j < H2D; j += 32) hsh[j] = h2[b * H2D + j];
    __syncthreads();

    float acc = 0.f;
    if (lane < NC) {
        acc = bd[lane];
#pragma unroll
        for (int j = 0; j < H2D; ++j) acc = fmaf(hsh[j], Wd[j * NC + lane], acc);
    }
    float v = (lane < NC) ? acc : -FLT_MAX;
#pragma unroll
    for (int off = 16; off > 0; off >>= 1)
        v = fmaxf(v, __shfl_xor_sync(0xffffffffu, v, off));
    float e = (lane < NC) ? expf(acc - v) : 0.f;
    float s = e;
#pragma unroll
    for (int off = 16; off > 0; off >>= 1)
        s += __shfl_xor_sync(0xffffffffu, s, off);
    if (lane < NC) out[b * NC + lane] = e / s;
}

// ---------------- launch ----------------------------------------------------
extern "C" void kernel_launch(void* const* d_in, const int* in_sizes, int n_in,
                              void* d_out, int out_size)
{
    const float* x  = (const float*)d_in[0];
    const float* W1 = (const float*)d_in[1];
    const float* U1 = (const float*)d_in[2];
    const float* b1 = (const float*)d_in[3];
    const float* W2 = (const float*)d_in[4];
    const float* U2 = (const float*)d_in[5];
    const float* b2 = (const float*)d_in[6];
    const float* Wd = (const float*)d_in[7];
    const float* bd = (const float*)d_in[8];
    float* out = (float*)d_out;

    const int gemm_smem  = (KMAX * AP + KMAX * BN) * 4;                 // 67584
    const int scan2_smem = (512 * U2P + 2 * 4 * H2D + 128 * ZSP) * 4;   // 153600
    cudaFuncSetAttribute(gemm_ff,    cudaFuncAttributeMaxDynamicSharedMemorySize, gemm_smem);
    cudaFuncSetAttribute(lstm_scan2, cudaFuncAttributeMaxDynamicSharedMemorySize, scan2_smem);

    float *zx1p, *h1p, *zx2p, *h2p;
    cudaGetSymbolAddress((void**)&zx1p, g_zx1);
    cudaGetSymbolAddress((void**)&h1p,  g_h1);
    cudaGetSymbolAddress((void**)&zx2p, g_zx2);
    cudaGetSymbolAddress((void**)&h2p,  g_h2);

    const int M = T_SEQ * BATCH;

    gemm_ff<<<dim3(M / BM, (G1D + BN - 1) / BN), 256, gemm_smem>>>(
        x, W1, b1, zx1p, M, G1D, IND, 1);

    lstm_scan1<<<BATCH / 4, 512>>>(zx1p, U1, h1p);

    gemm_ff<<<dim3(M / BM, G2D / BN), 256, gemm_smem>>>(
        h1p, W2, b2, zx2p, M, G2D, H1D, 0);

    lstm_scan2<<<BATCH / 4, 512, scan2_smem>>>(zx2p, U2, h2p);

    head_kernel<<<BATCH, 32>>>(h2p, Wd, bd, out);
}